// round 4
// baseline (speedup 1.0000x reference)
#include <cuda_runtime.h>
#include <cstdint>

#define K_DIM  8192
#define M_ROWS 128
#define N_COLS 8192
#define BN     64
#define BK     64
#define NK     (K_DIM / BK)    // 128
#define NBUF   3

// shared memory layout (floats)
// x:  [s][h][m:128][36]  packed fragment-major, stride 36 (conflict-free LDS.128)
// W:  [s][h][n:64][32]   R3 XOR-float4 swizzled, k-contiguous
// A:  [s][h][r:8][36]    packed like x (rows 4..7 zero)
#define XSTG   (2 * 128 * 36)                 // 9216
#define WSTG   (2 * 64 * 32)                  // 4096
#define ASTG   (2 * 8 * 36)                   // 576
#define XS_OFF 0
#define WS_OFF (NBUF * XSTG)                  // 27648
#define AS_OFF (WS_OFF + NBUF * WSTG)         // 39936
#define SMEM_FLOATS (AS_OFF + NBUF * ASTG)    // 41664 floats = 166656 B

__device__ float g_xt[M_ROWS * K_DIM];   // x, tf32, fragment-packed
__device__ float g_at[512 * K_DIM];      // lokr_A, tf32, fragment-packed

__device__ __forceinline__ uint32_t f2tf32(float f) {
    uint32_t u;
    asm("cvt.rna.tf32.f32 %0, %1;" : "=r"(u) : "f"(f));
    return u;
}

__device__ __forceinline__ uint32_t smem_u32(const void* p) {
    uint32_t a;
    asm("{ .reg .u64 t; cvta.to.shared.u64 t, %1; cvt.u32.u64 %0, t; }" : "=r"(a) : "l"(p));
    return a;
}

__device__ __forceinline__ void cp16(uint32_t dst, const void* src) {
    asm volatile("cp.async.cg.shared.global [%0], [%1], 16;" :: "r"(dst), "l"(src));
}

__device__ __forceinline__ void mma_tf32(float* d, const uint32_t* a, const uint32_t* b) {
    asm volatile(
        "mma.sync.aligned.m16n8k8.row.col.f32.tf32.tf32.f32 "
        "{%0,%1,%2,%3},{%4,%5,%6,%7},{%8,%9},{%0,%1,%2,%3};\n"
        : "+f"(d[0]), "+f"(d[1]), "+f"(d[2]), "+f"(d[3])
        : "r"(a[0]), "r"(a[1]), "r"(a[2]), "r"(a[3]), "r"(b[0]), "r"(b[1]));
}

// pack x: out idx = ((f*128+m)*2+h)*32 + q*8 + j  <-  x[m][f*64+h*32+q+4j]
__global__ void cvt_x_kernel(const float* __restrict__ x) {
    int i = blockIdx.x * blockDim.x + threadIdx.x;
    int j = i & 7, q = (i >> 3) & 3, h = (i >> 5) & 1, m = (i >> 6) & 127, f = i >> 13;
    int k = f * 64 + h * 32 + q + 4 * j;
    g_xt[i] = __uint_as_float(f2tf32(x[(size_t)m * K_DIM + k]));
}

// pack A: out idx = ((f*512+r)*2+h)*32 + q*8 + j  <-  A[r][f*64+h*32+q+4j]
__global__ void cvt_a_kernel(const float* __restrict__ A) {
    int i = blockIdx.x * blockDim.x + threadIdx.x;
    int j = i & 7, q = (i >> 3) & 3, h = (i >> 5) & 1, r = (i >> 6) & 511, f = i >> 15;
    int k = f * 64 + h * 32 + q + 4 * j;
    g_at[i] = __uint_as_float(f2tf32(A[(size_t)r * K_DIM + k]));
}

// out[m,n] = sum_k x[m,k]*W[n,k] + 2*s*B[n%16]*(x@A^T)[m, n/16]
__global__ __launch_bounds__(256, 1)
void lokr_gemm_kernel(const float* __restrict__ Wm,
                      const float* __restrict__ Bv,
                      const float* __restrict__ sc,
                      float* __restrict__ out)
{
    extern __shared__ float sm[];
    const uint32_t sb = smem_u32(sm);

    const int t    = threadIdx.x;
    const int lane = t & 31;
    const int warp = t >> 5;
    const int wm   = warp & 1;         // m half (64 rows)
    const int wn   = (warp >> 1) & 1;  // n half (32 cols)
    const int wk   = (warp >> 2) & 1;  // k half (32 of 64 per stage)
    const int q    = lane & 3;
    const int g    = lane >> 2;
    const int n0   = blockIdx.x * BN;

    // zero A pad rows (4..7) for all stages/halves, once
    for (int i = t; i < NBUF * ASTG / 2; i += 256) {   // 864 floats
        const int s = i / 288, rem = i % 288;
        const int h = rem / 144, rem2 = rem % 144;
        sm[AS_OFF + s * ASTG + h * 288 + (4 + rem2 / 36) * 36 + (rem2 % 36)] = 0.0f;
    }

    // fill-thread geometry (W path, R3-proven)
    const int kq = t & 7;
    const int rr = t >> 3;
    const float* wg = Wm + (size_t)(n0 + rr) * K_DIM + kq * 4;

    float4 wreg[2][4];
    #pragma unroll
    for (int slot = 0; slot < 2; ++slot)
        #pragma unroll
        for (int jm = 0; jm < 2; ++jm)
            #pragma unroll
            for (int h = 0; h < 2; ++h)
                wreg[slot][jm * 2 + h] = __ldcs(reinterpret_cast<const float4*>(
                    wg + (size_t)(32 * jm) * K_DIM + slot * BK + h * 32));

    auto fill = [&](int f) {
        const int s = f % NBUF;
        // W: cvt -> STS (XOR float4 swizzle), from ring loaded 2 stages earlier
        float4* wrp = wreg[f & 1];
        #pragma unroll
        for (int jm = 0; jm < 2; ++jm)
            #pragma unroll
            for (int h = 0; h < 2; ++h) {
                float4 v = wrp[jm * 2 + h];
                uint4 c;
                c.x = f2tf32(v.x); c.y = f2tf32(v.y); c.z = f2tf32(v.z); c.w = f2tf32(v.w);
                const uint32_t wd = sb + 4u * (WS_OFF + s * WSTG + h * 2048 + (jm * 32 + rr) * 32)
                                    + ((uint32_t)(kq ^ (rr & 7)) << 4);
                asm volatile("st.shared.v4.b32 [%0], {%1,%2,%3,%4};"
                             :: "r"(wd), "r"(c.x), "r"(c.y), "r"(c.z), "r"(c.w));
            }
        if (f + 2 < NK) {
            const float* p = wg + (size_t)(f + 2) * BK;
            #pragma unroll
            for (int jm = 0; jm < 2; ++jm)
                #pragma unroll
                for (int h = 0; h < 2; ++h)
                    wrp[jm * 2 + h] = __ldcs(reinterpret_cast<const float4*>(
                        p + (size_t)(32 * jm) * K_DIM + h * 32));
        }
        // x tile: 2048 16B chunks from packed g_xt
        #pragma unroll
        for (int i = 0; i < 8; ++i) {
            const int c = t + 256 * i;
            const int m = c >> 4, r = c & 15;
            const int h = r >> 3, qq = (r >> 1) & 3, j4 = (r & 1) * 4;
            const uint32_t xd = sb + 4u * (XS_OFF + s * XSTG + h * 4608 + m * 36 + qq * 8 + j4);
            cp16(xd, g_xt + (size_t)f * 8192 + (size_t)c * 4);
        }
        // A tile: 64 chunks (4 real rows)
        if (t < 64) {
            const int r = t >> 4, rc = t & 15;
            const int h = rc >> 3, qq = (rc >> 1) & 3, j4 = (rc & 1) * 4;
            const uint32_t ad = sb + 4u * (AS_OFF + s * ASTG + h * 288 + r * 36 + qq * 8 + j4);
            cp16(ad, g_at + (size_t)f * 32768 + (size_t)(blockIdx.x * 4 + r) * 64 + rc * 4);
        }
        asm volatile("cp.async.commit_group;");
    };

    fill(0);
    fill(1);

    float acc[4][4][4];
    float yac[4][4];
    #pragma unroll
    for (int mt = 0; mt < 4; ++mt) {
        #pragma unroll
        for (int nt = 0; nt < 4; ++nt)
            #pragma unroll
            for (int r = 0; r < 4; ++r) acc[mt][nt][r] = 0.0f;
        #pragma unroll
        for (int r = 0; r < 4; ++r) yac[mt][r] = 0.0f;
    }

    for (int kt = 0; kt < NK; ++kt) {
        if (kt + 1 < NK) asm volatile("cp.async.wait_group 1;");
        else             asm volatile("cp.async.wait_group 0;");
        __syncthreads();

        const int s = kt % NBUF;
        const float* xb = sm + XS_OFF + s * XSTG + wk * 4608;
        const float* wb = sm + WS_OFF + s * WSTG + wk * 2048;
        const float* ab = sm + AS_OFF + s * ASTG + wk * 288;

        #pragma unroll
        for (int jb = 0; jb < 2; ++jb) {
            float4 ax[4][2];
            #pragma unroll
            for (int mt = 0; mt < 4; ++mt) {
                const int mrow = wm * 64 + mt * 16 + g;
                ax[mt][0] = *reinterpret_cast<const float4*>(xb + mrow * 36 + q * 8 + jb * 4);
                ax[mt][1] = *reinterpret_cast<const float4*>(xb + (mrow + 8) * 36 + q * 8 + jb * 4);
            }
            const float4 bex = *reinterpret_cast<const float4*>(ab + g * 36 + q * 8 + jb * 4);
            #pragma unroll
            for (int kgi = 0; kgi < 2; ++kgi) {
                const int kg = jb * 2 + kgi;
                const int c0 = (kg * 8 + q) ^ (g * 4);
                const int c1 = c0 ^ 4;
                uint32_t bw[4][2];
                #pragma unroll
                for (int nt = 0; nt < 4; ++nt) {
                    const float* bp = wb + (wn * 32 + nt * 8 + g) * 32;
                    bw[nt][0] = __float_as_uint(bp[c0]);
                    bw[nt][1] = __float_as_uint(bp[c1]);
                }
                uint32_t beu[2];
                beu[0] = __float_as_uint(kgi ? bex.z : bex.x);
                beu[1] = __float_as_uint(kgi ? bex.w : bex.y);
                #pragma unroll
                for (int mt = 0; mt < 4; ++mt) {
                    uint32_t af[4];
                    af[0] = __float_as_uint(kgi ? ax[mt][0].z : ax[mt][0].x);
                    af[1] = __float_as_uint(kgi ? ax[mt][1].z : ax[mt][1].x);
                    af[2] = __float_as_uint(kgi ? ax[mt][0].w : ax[mt][0].y);
                    af[3] = __float_as_uint(kgi ? ax[mt][1].w : ax[mt][1].y);
                    #pragma unroll
                    for (int nt = 0; nt < 4; ++nt)
                        mma_tf32(acc[mt][nt], af, bw[nt]);
                    mma_tf32(yac[mt], af, beu);
                }
            }
        }
        __syncthreads();
        if (kt + 2 < NK) fill(kt + 2);
    }

    // ---- k-reduction across wk pairs through smem scratch ----
    float* scr = sm;   // safe after final sync: all reads of stage buffers done
    if (wk == 1) {
        const int pos = warp - 4;
        float* as_ = scr + pos * 2080 + lane * 65;
        #pragma unroll
        for (int mt = 0; mt < 4; ++mt)
            #pragma unroll
            for (int nt = 0; nt < 4; ++nt)
                #pragma unroll
                for (int r = 0; r < 4; ++r)
                    as_[(mt * 4 + nt) * 4 + r] = acc[mt][nt][r];
        float* ys = scr + 8320 + pos * 544 + lane * 17;
        #pragma unroll
        for (int mt = 0; mt < 4; ++mt)
            #pragma unroll
            for (int r = 0; r < 4; ++r)
                ys[mt * 4 + r] = yac[mt][r];
    }
    __syncthreads();
    if (wk == 0) {
        const int pos = warp;
        const float* as_ = scr + pos * 2080 + lane * 65;
        #pragma unroll
        for (int mt = 0; mt < 4; ++mt)
            #pragma unroll
            for (int nt = 0; nt < 4; ++nt)
                #pragma unroll
                for (int r = 0; r < 4; ++r)
                    acc[mt][nt][r] += as_[(mt * 4 + nt) * 4 + r];
        const float* ys = scr + 8320 + pos * 544 + lane * 17;
        #pragma unroll
        for (int mt = 0; mt < 4; ++mt)
            #pragma unroll
            for (int r = 0; r < 4; ++r)
                yac[mt][r] += ys[mt * 4 + r];

        // ---- epilogue: out = acc + cf[n%16] * y[m, n/16] ----
        const float s2 = 2.0f * sc[0];
        const float cfe0 = s2 * Bv[2 * q];
        const float cfe1 = s2 * Bv[2 * q + 1];
        const float cfo0 = s2 * Bv[8 + 2 * q];
        const float cfo1 = s2 * Bv[9 + 2 * q];

        #pragma unroll
        for (int mt = 0; mt < 4; ++mt) {
            const int srcl = g * 4 + wn;
            const float yA0 = __shfl_sync(0xFFFFFFFFu, yac[mt][0], srcl);
            const float yA1 = __shfl_sync(0xFFFFFFFFu, yac[mt][1], srcl);
            const float yB0 = __shfl_sync(0xFFFFFFFFu, yac[mt][2], srcl);
            const float yB1 = __shfl_sync(0xFFFFFFFFu, yac[mt][3], srcl);
            #pragma unroll
            for (int nt = 0; nt < 4; ++nt) {
                const float yg  = (nt < 2) ? yA0 : yA1;
                const float yg8 = (nt < 2) ? yB0 : yB1;
                const float f0 = (nt & 1) ? cfo0 : cfe0;
                const float f1 = (nt & 1) ? cfo1 : cfe1;
                const int m = wm * 64 + mt * 16 + g;
                const int n = n0 + wn * 32 + nt * 8 + 2 * q;
                float2 v0 = make_float2(acc[mt][nt][0] + f0 * yg, acc[mt][nt][1] + f1 * yg);
                float2 v1 = make_float2(acc[mt][nt][2] + f0 * yg8, acc[mt][nt][3] + f1 * yg8);
                *reinterpret_cast<float2*>(out + (size_t)m * N_COLS + n) = v0;
                *reinterpret_cast<float2*>(out + (size_t)(m + 8) * N_COLS + n) = v1;
            }
        }
    }
}

extern "C" void kernel_launch(void* const* d_in, const int* in_sizes, int n_in,
                              void* d_out, int out_size) {
    const float* x  = (const float*)d_in[0];   // (128, 8192)
    const float* Wm = (const float*)d_in[1];   // (8192, 8192)
    const float* Am = (const float*)d_in[2];   // (512, 8192)
    const float* Bv = (const float*)d_in[3];   // (16, 1)
    const float* sc = (const float*)d_in[4];   // (1,)
    float* out = (float*)d_out;                // (128, 8192)

    cudaFuncSetAttribute(lokr_gemm_kernel,
                         cudaFuncAttributeMaxDynamicSharedMemorySize,
                         SMEM_FLOATS * 4);

    cvt_x_kernel<<<(M_ROWS * K_DIM) / 256, 256>>>(x);
    cvt_a_kernel<<<(512 * K_DIM) / 256, 256>>>(Am);
    lokr_gemm_kernel<<<N_COLS / BN, 256, SMEM_FLOATS * 4>>>(Wm, Bv, sc, out);
}